// round 15
// baseline (speedup 1.0000x reference)
#include <cuda_runtime.h>
#include <cuda_fp16.h>
#include <cstdint>
#include <cstddef>

#define MDIM 8192
#define NDIM 2048
#define KDIM 2048

#define BM 128
#define BN 128
#define NS 32               // 2048/64 halfs per stage
#define STAGE_BYTES 32768   // A 16KB + B 16KB
#define NSTAGES 3
#define SM_BYTES (NSTAGES * STAGE_BYTES)

#define TAU 0.05f
#define FLIST_CAP 2048

#define PREP_A_BLOCKS 16384
#define PREP_B_BLOCKS 2048

__device__ __half g_A2[(size_t)MDIM * KDIM];   // [m][k]: fp16(x)
__device__ __half g_B2[(size_t)NDIM * KDIM];   // [n][k]: sign(W) as fp16 (n-major)

// ---------------- helpers ----------------
__device__ __forceinline__ uint32_t smem_u32(const void* p) {
    uint32_t a;
    asm("{ .reg .u64 t; cvta.to.shared.u64 t, %1; cvt.u32.u64 %0, t; }" : "=r"(a) : "l"(p));
    return a;
}
__device__ __forceinline__ uint32_t swz(uint32_t off) { return off ^ ((off >> 3) & 0x70); }

__device__ __forceinline__ void ldsm4(uint32_t* r, uint32_t addr) {
    asm volatile("ldmatrix.sync.aligned.m8n8.x4.shared.b16 {%0,%1,%2,%3}, [%4];"
                 : "=r"(r[0]), "=r"(r[1]), "=r"(r[2]), "=r"(r[3]) : "r"(addr));
}

__device__ __forceinline__ void mma16816(float* c, const uint32_t* a, uint32_t b0, uint32_t b1) {
    asm volatile(
        "mma.sync.aligned.m16n8k16.row.col.f32.f16.f16.f32 "
        "{%0,%1,%2,%3}, {%4,%5,%6,%7}, {%8,%9}, {%0,%1,%2,%3};"
        : "+f"(c[0]), "+f"(c[1]), "+f"(c[2]), "+f"(c[3])
        : "r"(a[0]), "r"(a[1]), "r"(a[2]), "r"(a[3]), "r"(b0), "r"(b1));
}

__device__ __forceinline__ void cp16(uint32_t dst, const void* src) {
    asm volatile("cp.async.cg.shared.global [%0], [%1], 16;" :: "r"(dst), "l"(src));
}
#define CP_COMMIT() asm volatile("cp.async.commit_group;" ::: "memory")
#define CP_WAIT1()  asm volatile("cp.async.wait_group 1;" ::: "memory")
#define CP_WAIT0()  asm volatile("cp.async.wait_group 0;" ::: "memory")

// ---------------- fused prep: A -> fp16, B -> transposed signs ----------------
__global__ void __launch_bounds__(256) prep_kernel(const float* __restrict__ x,
                                                   const float* __restrict__ W) {
    __shared__ float tile[64][33];
    const int b = blockIdx.x;
    const int t = threadIdx.x;

    if (b < PREP_A_BLOCKS) {
        const size_t i = (size_t)b * 256 + t;
        float4 v = reinterpret_cast<const float4*>(x)[i];
        __half2 h0 = __floats2half2_rn(v.x, v.y);
        __half2 h1 = __floats2half2_rn(v.z, v.w);
        uint2 pk;
        pk.x = *reinterpret_cast<uint32_t*>(&h0);
        pk.y = *reinterpret_cast<uint32_t*>(&h1);
        reinterpret_cast<uint2*>(g_A2)[i] = pk;
    } else {
        const int bi = b - PREP_A_BLOCKS;
        const int k0 = (bi & 31) * 64;
        const int n0 = (bi >> 5) * 32;
        #pragma unroll
        for (int j = 0; j < 8; j++) {
            const int idx = t + j * 256;
            const int row = idx >> 5, col = idx & 31;
            tile[row][col] = W[(size_t)(k0 + row) * NDIM + (n0 + col)];
        }
        __syncthreads();
        #pragma unroll
        for (int j = 0; j < 4; j++) {
            const int idx = t + j * 256;
            const int nr = idx >> 5, kc = idx & 31;
            float w0 = tile[2 * kc][nr];
            float w1 = tile[2 * kc + 1][nr];
            float s0 = (w0 > 0.0f) ? 1.0f : ((w0 < 0.0f) ? -1.0f : 0.0f);
            float s1 = (w1 > 0.0f) ? 1.0f : ((w1 < 0.0f) ? -1.0f : 0.0f);
            reinterpret_cast<__half2*>(g_B2 + (size_t)(n0 + nr) * KDIM + k0)[kc] =
                __floats2half2_rn(s0, s1);
        }
    }
}

// ---------------- GEMM: 128x128 tile, 128 thr (2Mx2N warps of 64x64), 3-stage ----------------
__global__ void __launch_bounds__(128, 2) bgemm_kernel(const float* __restrict__ x,
                                                       float* __restrict__ out) {
    extern __shared__ char smem[];
    const uint32_t sb = smem_u32(smem);
    const int tid = threadIdx.x;
    const int wid = tid >> 5;
    const int l   = tid & 31;
    const int wm  = wid & 1;   // 2 warps over M (64 rows each)
    const int wn  = wid >> 1;  // 2 warps over N (64 cols each)
    const int m0 = blockIdx.x * BM;
    const int n0 = blockIdx.y * BN;

    const uint4* a_src = reinterpret_cast<const uint4*>(g_A2);  // row stride 256 uint4
    const uint4* b_src = reinterpret_cast<const uint4*>(g_B2);

    uint32_t aoff[4], boff[4];
    #pragma unroll
    for (int mf = 0; mf < 4; mf++)
        aoff[mf] = (uint32_t)(wm * 64 + mf * 16 + (l & 15)) * 128 + (uint32_t)((l >> 4) & 1) * 16;
    #pragma unroll
    for (int bg = 0; bg < 4; bg++)
        boff[bg] = (uint32_t)(wn * 64 + bg * 16 + (l & 7) + ((l >> 4) & 1) * 8) * 128
                 + (uint32_t)((l >> 3) & 1) * 16;

    float c[4][8][4];
    #pragma unroll
    for (int i = 0; i < 4; i++)
        #pragma unroll
        for (int j = 0; j < 8; j++)
            #pragma unroll
            for (int e = 0; e < 4; e++) c[i][j][e] = 0.0f;

    auto issue_stage = [&](int s, int slot) {
        const uint32_t Ab = sb + (uint32_t)slot * STAGE_BYTES;
        const uint32_t Bb = Ab + 16384;
        #pragma unroll
        for (int i = 0; i < 8; i++) {
            const int cch = tid + i * 128;
            const int row = cch >> 3, j = cch & 7;
            cp16(Ab + swz((uint32_t)row * 128 + j * 16),
                 a_src + (size_t)(m0 + row) * 256 + s * 8 + j);
            cp16(Bb + swz((uint32_t)row * 128 + j * 16),
                 b_src + (size_t)(n0 + row) * 256 + s * 8 + j);
        }
        CP_COMMIT();
    };

    issue_stage(0, 0);
    issue_stage(1, 1);

    int slot = 0;
    for (int s = 0; s < NS; s++) {
        CP_WAIT1();
        __syncthreads();
        if (s + 2 < NS) {
            int ns = slot + 2; if (ns >= 3) ns -= 3;
            issue_stage(s + 2, ns);
        }

        const uint32_t Ab = sb + (uint32_t)slot * STAGE_BYTES;
        const uint32_t Bb = Ab + 16384;
        #pragma unroll
        for (int ks = 0; ks < 4; ks++) {
            uint32_t af[4][4], bq[4][4];
            #pragma unroll
            for (int mf = 0; mf < 4; mf++)
                ldsm4(af[mf], Ab + swz(aoff[mf] + ks * 32));
            #pragma unroll
            for (int bg = 0; bg < 4; bg++)
                ldsm4(bq[bg], Bb + swz(boff[bg] + ks * 32));
            #pragma unroll
            for (int mf = 0; mf < 4; mf++)
                #pragma unroll
                for (int nf = 0; nf < 8; nf++)
                    mma16816(c[mf][nf], af[mf], bq[nf >> 1][(nf & 1) * 2], bq[nf >> 1][(nf & 1) * 2 + 1]);
        }
        if (++slot == 3) slot = 0;
    }
    CP_WAIT0();
    __syncthreads();   // ldsm reads done -> stage smem reusable for flag list

    // ---- flag list in (dead) stage smem ----
    int*  fcnt  = reinterpret_cast<int*>(smem);
    int2* flist = reinterpret_cast<int2*>(smem + 16);
    if (tid == 0) *fcnt = 0;
    __syncthreads();

    // ---- epilogue: sign + near-zero flagging ----
    const int g  = l >> 2;
    const int tg = l & 3;
    #pragma unroll
    for (int mf = 0; mf < 4; mf++) {
        const int r0 = m0 + wm * 64 + mf * 16 + g;
        #pragma unroll
        for (int nf = 0; nf < 8; nf++) {
            const int col = n0 + wn * 64 + nf * 8 + 2 * tg;
            #pragma unroll
            for (int e = 0; e < 4; e++) {
                float v = c[mf][nf][e];
                if (fabsf(v) < TAU) {
                    int idx = atomicAdd(fcnt, 1);
                    if (idx < FLIST_CAP)
                        flist[idx] = make_int2(r0 + (e >> 1) * 8, col + (e & 1));
                }
            }
            float2 lo, hi;
            lo.x = (c[mf][nf][0] > 0.0f) ? 1.0f : ((c[mf][nf][0] < 0.0f) ? -1.0f : 0.0f);
            lo.y = (c[mf][nf][1] > 0.0f) ? 1.0f : ((c[mf][nf][1] < 0.0f) ? -1.0f : 0.0f);
            hi.x = (c[mf][nf][2] > 0.0f) ? 1.0f : ((c[mf][nf][2] < 0.0f) ? -1.0f : 0.0f);
            hi.y = (c[mf][nf][3] > 0.0f) ? 1.0f : ((c[mf][nf][3] < 0.0f) ? -1.0f : 0.0f);
            *reinterpret_cast<float2*>(out + (size_t)r0 * NDIM + col) = lo;
            *reinterpret_cast<float2*>(out + (size_t)(r0 + 8) * NDIM + col) = hi;
        }
    }
    __syncthreads();

    // ---- exact fp64 recompute of this CTA's flagged outputs (warp per flag) ----
    int cnt = *fcnt;
    if (cnt > FLIST_CAP) cnt = FLIST_CAP;
    for (int i = wid; i < cnt; i += 4) {
        const int m = flist[i].x;
        const int n = flist[i].y;
        const float4* xr = reinterpret_cast<const float4*>(x + (size_t)m * KDIM);
        const __half2* sr = reinterpret_cast<const __half2*>(g_B2 + (size_t)n * KDIM);
        double acc = 0.0;
        #pragma unroll 4
        for (int k4 = l; k4 < KDIM / 4; k4 += 32) {
            float4 xv = xr[k4];
            __half2 s0 = sr[k4 * 2];
            __half2 s1 = sr[k4 * 2 + 1];
            float2 f0 = __half22float2(s0);
            float2 f1 = __half22float2(s1);
            acc += (double)(xv.x * f0.x) + (double)(xv.y * f0.y)
                 + (double)(xv.z * f1.x) + (double)(xv.w * f1.y);
        }
        #pragma unroll
        for (int o = 16; o; o >>= 1) acc += __shfl_down_sync(0xFFFFFFFFu, acc, o);
        if (l == 0)
            out[(size_t)m * NDIM + n] = (acc > 0.0) ? 1.0f : ((acc < 0.0) ? -1.0f : 0.0f);
    }
}

// ---------------- launch ----------------
extern "C" void kernel_launch(void* const* d_in, const int* in_sizes, int n_in,
                              void* d_out, int out_size) {
    const float* x = (const float*)d_in[0];
    const float* W = (const float*)d_in[1];
    float* out = (float*)d_out;

    cudaFuncSetAttribute(bgemm_kernel, cudaFuncAttributeMaxDynamicSharedMemorySize, SM_BYTES);

    prep_kernel<<<PREP_A_BLOCKS + PREP_B_BLOCKS, 256>>>(x, W);
    bgemm_kernel<<<dim3(MDIM / BM, NDIM / BN), 128, SM_BYTES>>>(x, out);
}

// round 17
// speedup vs baseline: 1.0834x; 1.0834x over previous
#include <cuda_runtime.h>
#include <cuda_fp16.h>
#include <cstdint>
#include <cstddef>

#define MDIM 8192
#define NDIM 2048
#define KDIM 2048

#define BM 128
#define BN 128
#define NS 64               // 2048/32 halfs per stage
#define STAGE_BYTES 16384   // A 8KB + B 8KB (64B rows)
#define NSTAGES 6
#define SM_BYTES (NSTAGES * STAGE_BYTES)   // 96KB

#define TAU 0.05f
#define FLIST_CAP 2048

#define PREP_A_BLOCKS 16384
#define PREP_B_BLOCKS 2048

__device__ __half g_A2[(size_t)MDIM * KDIM];   // [m][k]: fp16(x)
__device__ __half g_B2[(size_t)NDIM * KDIM];   // [n][k]: sign(W) as fp16 (n-major)

// ---------------- helpers ----------------
__device__ __forceinline__ uint32_t smem_u32(const void* p) {
    uint32_t a;
    asm("{ .reg .u64 t; cvta.to.shared.u64 t, %1; cvt.u32.u64 %0, t; }" : "=r"(a) : "l"(p));
    return a;
}
// SW64 swizzle for 64-byte rows: XOR 16B-chunk bits [4:5] with row bits [7:8]
__device__ __forceinline__ uint32_t swz64(uint32_t off) { return off ^ ((off >> 3) & 0x30); }

__device__ __forceinline__ void ldsm4(uint32_t* r, uint32_t addr) {
    asm volatile("ldmatrix.sync.aligned.m8n8.x4.shared.b16 {%0,%1,%2,%3}, [%4];"
                 : "=r"(r[0]), "=r"(r[1]), "=r"(r[2]), "=r"(r[3]) : "r"(addr));
}

__device__ __forceinline__ void mma16816(float* c, const uint32_t* a, uint32_t b0, uint32_t b1) {
    asm volatile(
        "mma.sync.aligned.m16n8k16.row.col.f32.f16.f16.f32 "
        "{%0,%1,%2,%3}, {%4,%5,%6,%7}, {%8,%9}, {%0,%1,%2,%3};"
        : "+f"(c[0]), "+f"(c[1]), "+f"(c[2]), "+f"(c[3])
        : "r"(a[0]), "r"(a[1]), "r"(a[2]), "r"(a[3]), "r"(b0), "r"(b1));
}

__device__ __forceinline__ void cp16(uint32_t dst, const void* src) {
    asm volatile("cp.async.cg.shared.global [%0], [%1], 16;" :: "r"(dst), "l"(src));
}
#define CP_COMMIT() asm volatile("cp.async.commit_group;" ::: "memory")
#define CP_WAIT4()  asm volatile("cp.async.wait_group 4;" ::: "memory")
#define CP_WAIT0()  asm volatile("cp.async.wait_group 0;" ::: "memory")

// ---------------- fused prep: A -> fp16, B -> transposed signs ----------------
__global__ void __launch_bounds__(256) prep_kernel(const float* __restrict__ x,
                                                   const float* __restrict__ W) {
    __shared__ float tile[64][33];
    const int b = blockIdx.x;
    const int t = threadIdx.x;

    if (b < PREP_A_BLOCKS) {
        const size_t i = (size_t)b * 256 + t;
        float4 v = reinterpret_cast<const float4*>(x)[i];
        __half2 h0 = __floats2half2_rn(v.x, v.y);
        __half2 h1 = __floats2half2_rn(v.z, v.w);
        uint2 pk;
        pk.x = *reinterpret_cast<uint32_t*>(&h0);
        pk.y = *reinterpret_cast<uint32_t*>(&h1);
        reinterpret_cast<uint2*>(g_A2)[i] = pk;
    } else {
        const int bi = b - PREP_A_BLOCKS;
        const int k0 = (bi & 31) * 64;
        const int n0 = (bi >> 5) * 32;
        #pragma unroll
        for (int j = 0; j < 8; j++) {
            const int idx = t + j * 256;
            const int row = idx >> 5, col = idx & 31;
            tile[row][col] = W[(size_t)(k0 + row) * NDIM + (n0 + col)];
        }
        __syncthreads();
        #pragma unroll
        for (int j = 0; j < 4; j++) {
            const int idx = t + j * 256;
            const int nr = idx >> 5, kc = idx & 31;
            float w0 = tile[2 * kc][nr];
            float w1 = tile[2 * kc + 1][nr];
            float s0 = (w0 > 0.0f) ? 1.0f : ((w0 < 0.0f) ? -1.0f : 0.0f);
            float s1 = (w1 > 0.0f) ? 1.0f : ((w1 < 0.0f) ? -1.0f : 0.0f);
            reinterpret_cast<__half2*>(g_B2 + (size_t)(n0 + nr) * KDIM + k0)[kc] =
                __floats2half2_rn(s0, s1);
        }
    }
}

// ---------------- GEMM: 128x128 tile, 256 thr (4Mx2N warps of 32x64), 6-stage BK=32 ----------------
__global__ void __launch_bounds__(256, 2) bgemm_kernel(const float* __restrict__ x,
                                                       float* __restrict__ out) {
    extern __shared__ char smem[];
    const uint32_t sb = smem_u32(smem);
    const int tid = threadIdx.x;
    const int wid = tid >> 5;
    const int l   = tid & 31;
    const int wm  = wid & 3;   // 4 warps over M (32 rows each)
    const int wn  = wid >> 2;  // 2 warps over N (64 cols each)
    const int m0 = blockIdx.x * BM;
    const int n0 = blockIdx.y * BN;

    const uint4* a_src = reinterpret_cast<const uint4*>(g_A2);  // row = 256 uint4
    const uint4* b_src = reinterpret_cast<const uint4*>(g_B2);

    uint32_t aoff[2], boff[4];
    #pragma unroll
    for (int mf = 0; mf < 2; mf++)
        aoff[mf] = (uint32_t)(wm * 32 + mf * 16 + (l & 15)) * 64 + (uint32_t)((l >> 4) & 1) * 16;
    #pragma unroll
    for (int bg = 0; bg < 4; bg++)
        boff[bg] = (uint32_t)(wn * 64 + bg * 16 + (l & 7) + ((l >> 4) & 1) * 8) * 64
                 + (uint32_t)((l >> 3) & 1) * 16;

    float c[2][8][4];
    #pragma unroll
    for (int i = 0; i < 2; i++)
        #pragma unroll
        for (int j = 0; j < 8; j++)
            #pragma unroll
            for (int e = 0; e < 4; e++) c[i][j][e] = 0.0f;

    // one stage = BK=32 halfs = 4x 16B chunks per row; A 512 chunks + B 512 chunks
    auto issue_stage = [&](int s, int slot) {
        const uint32_t Ab = sb + (uint32_t)slot * STAGE_BYTES;
        const uint32_t Bb = Ab + 8192;
        #pragma unroll
        for (int i = 0; i < 2; i++) {
            const int cch = tid + i * 256;
            const int row = cch >> 2, j = cch & 3;
            cp16(Ab + swz64((uint32_t)row * 64 + j * 16),
                 a_src + (size_t)(m0 + row) * 256 + s * 4 + j);
            cp16(Bb + swz64((uint32_t)row * 64 + j * 16),
                 b_src + (size_t)(n0 + row) * 256 + s * 4 + j);
        }
        CP_COMMIT();
    };

    issue_stage(0, 0);
    issue_stage(1, 1);
    issue_stage(2, 2);
    issue_stage(3, 3);
    issue_stage(4, 4);

    int slot = 0;
    for (int s = 0; s < NS; s++) {
        CP_WAIT4();
        __syncthreads();
        if (s + 5 < NS) {
            int ns = slot + 5; if (ns >= 6) ns -= 6;
            issue_stage(s + 5, ns);
        }

        const uint32_t Ab = sb + (uint32_t)slot * STAGE_BYTES;
        const uint32_t Bb = Ab + 8192;
        #pragma unroll
        for (int ks = 0; ks < 2; ks++) {
            uint32_t af[2][4], bq[4][4];
            #pragma unroll
            for (int mf = 0; mf < 2; mf++)
                ldsm4(af[mf], Ab + swz64(aoff[mf] + ks * 32));
            #pragma unroll
            for (int bg = 0; bg < 4; bg++)
                ldsm4(bq[bg], Bb + swz64(boff[bg] + ks * 32));
            #pragma unroll
            for (int mf = 0; mf < 2; mf++)
                #pragma unroll
                for (int nf = 0; nf < 8; nf++)
                    mma16816(c[mf][nf], af[mf], bq[nf >> 1][(nf & 1) * 2], bq[nf >> 1][(nf & 1) * 2 + 1]);
        }
        if (++slot == 6) slot = 0;
    }
    CP_WAIT0();
    __syncthreads();   // ldsm reads done -> stage smem reusable for flag list

    // ---- flag list in (dead) stage smem ----
    int*  fcnt  = reinterpret_cast<int*>(smem);
    int2* flist = reinterpret_cast<int2*>(smem + 16);
    if (tid == 0) *fcnt = 0;
    __syncthreads();

    // ---- epilogue: sign + near-zero flagging ----
    const int g  = l >> 2;
    const int tg = l & 3;
    #pragma unroll
    for (int mf = 0; mf < 2; mf++) {
        const int r0 = m0 + wm * 32 + mf * 16 + g;
        #pragma unroll
        for (int nf = 0; nf < 8; nf++) {
            const int col = n0 + wn * 64 + nf * 8 + 2 * tg;
            #pragma unroll
            for (int e = 0; e < 4; e++) {
                float v = c[mf][nf][e];
                if (fabsf(v) < TAU) {
                    int idx = atomicAdd(fcnt, 1);
                    if (idx < FLIST_CAP)
                        flist[idx] = make_int2(r0 + (e >> 1) * 8, col + (e & 1));
                }
            }
            float2 lo, hi;
            lo.x = (c[mf][nf][0] > 0.0f) ? 1.0f : ((c[mf][nf][0] < 0.0f) ? -1.0f : 0.0f);
            lo.y = (c[mf][nf][1] > 0.0f) ? 1.0f : ((c[mf][nf][1] < 0.0f) ? -1.0f : 0.0f);
            hi.x = (c[mf][nf][2] > 0.0f) ? 1.0f : ((c[mf][nf][2] < 0.0f) ? -1.0f : 0.0f);
            hi.y = (c[mf][nf][3] > 0.0f) ? 1.0f : ((c[mf][nf][3] < 0.0f) ? -1.0f : 0.0f);
            *reinterpret_cast<float2*>(out + (size_t)r0 * NDIM + col) = lo;
            *reinterpret_cast<float2*>(out + (size_t)(r0 + 8) * NDIM + col) = hi;
        }
    }
    __syncthreads();

    // ---- exact fp64 recompute of this CTA's flagged outputs (warp per flag) ----
    int cnt = *fcnt;
    if (cnt > FLIST_CAP) cnt = FLIST_CAP;
    for (int i = wid; i < cnt; i += 8) {
        const int m = flist[i].x;
        const int n = flist[i].y;
        const float4* xr = reinterpret_cast<const float4*>(x + (size_t)m * KDIM);
        const __half2* sr = reinterpret_cast<const __half2*>(g_B2 + (size_t)n * KDIM);
        double acc = 0.0;
        #pragma unroll 4
        for (int k4 = l; k4 < KDIM / 4; k4 += 32) {
            float4 xv = xr[k4];
            __half2 s0 = sr[k4 * 2];
            __half2 s1 = sr[k4 * 2 + 1];
            float2 f0 = __half22float2(s0);
            float2 f1 = __half22float2(s1);
            acc += (double)(xv.x * f0.x) + (double)(xv.y * f0.y)
                 + (double)(xv.z * f1.x) + (double)(xv.w * f1.y);
        }
        #pragma unroll
        for (int o = 16; o; o >>= 1) acc += __shfl_down_sync(0xFFFFFFFFu, acc, o);
        if (l == 0)
            out[(size_t)m * NDIM + n] = (acc > 0.0) ? 1.0f : ((acc < 0.0) ? -1.0f : 0.0f);
    }
}

// ---------------- launch ----------------
extern "C" void kernel_launch(void* const* d_in, const int* in_sizes, int n_in,
                              void* d_out, int out_size) {
    const float* x = (const float*)d_in[0];
    const float* W = (const float*)d_in[1];
    float* out = (float*)d_out;

    cudaFuncSetAttribute(bgemm_kernel, cudaFuncAttributeMaxDynamicSharedMemorySize, SM_BYTES);

    prep_kernel<<<PREP_A_BLOCKS + PREP_B_BLOCKS, 256>>>(x, W);
    bgemm_kernel<<<dim3(MDIM / BM, NDIM / BN), 256, SM_BYTES>>>(x, out);
}